// round 1
// baseline (speedup 1.0000x reference)
#include <cuda_runtime.h>
#include <cstdint>

// Problem constants (fixed shapes)
#define Nb   16
#define C    30
#define H    128
#define W    128
#define HW   (H*W)            // 16384
#define TOT  (HW*C)           // 491520 per batch
#define K    1000
#define NBINS 2048
#define BSHIFT 13
#define LOBITS 0x3E99999Au    // __float_as_uint(0.3f)
#define CAP  2048
#define TH   0.3f

// Static scratch (no allocations allowed)
__device__ unsigned int       g_hist[Nb*NBINS];   // 128 KB
__device__ unsigned int       g_cnt[Nb];
__device__ int                g_cut[Nb];
__device__ unsigned long long g_buf[Nb*CAP];      // 256 KB

__device__ __forceinline__ float sigm(float x) {
    return 1.0f / (1.0f + expf(-x));
}

// ---------------------------------------------------------------- kernel 0
__global__ void zero_kernel() {
    int i = blockIdx.x * blockDim.x + threadIdx.x;
    if (i < Nb*NBINS) g_hist[i] = 0u;
}

// ---------------------------------------------------------------- kernel 1: histogram of score bits
__global__ void hist_kernel(const float* __restrict__ sCls) {
    __shared__ unsigned int sh[NBINS];
    const int b = blockIdx.y;
    for (int i = threadIdx.x; i < NBINS; i += blockDim.x) sh[i] = 0u;
    __syncthreads();

    const float4* p = (const float4*)(sCls + (size_t)b * TOT);
    const int nv4 = TOT / 4;                 // 122880
    const int per = nv4 / gridDim.x;         // gridDim.x = 32 -> 3840
    const int start = blockIdx.x * per;
    for (int i = start + threadIdx.x; i < start + per; i += blockDim.x) {
        float4 v = p[i];
        float vv[4] = {v.x, v.y, v.z, v.w};
        #pragma unroll
        for (int j = 0; j < 4; j++) {
            float s = sigm(vv[j]);
            if (s > TH) {
                unsigned int bin = (__float_as_uint(s) - LOBITS) >> BSHIFT;
                if (bin > NBINS-1u) bin = NBINS-1u;
                atomicAdd(&sh[bin], 1u);
            }
        }
    }
    __syncthreads();
    for (int i = threadIdx.x; i < NBINS; i += blockDim.x) {
        unsigned int c = sh[i];
        if (c) atomicAdd(&g_hist[b*NBINS + i], c);
    }
}

// ---------------------------------------------------------------- kernel 2: find cut bin (descending scan), reset counters
__global__ void cut_kernel() {
    const int b = blockIdx.x;       // 16 blocks, 256 threads
    const int t = threadIdx.x;
    __shared__ unsigned int warp_sums[8];
    __shared__ unsigned int s_total;

    unsigned int c[8];
    unsigned int S = 0;
    const int base = b * NBINS;
    #pragma unroll
    for (int i = 0; i < 8; i++) {
        int r = t*8 + i;                        // reversed index: r=0 is highest bin
        c[i] = g_hist[base + (NBINS-1 - r)];
        S += c[i];
    }
    // inclusive warp scan of S
    unsigned int x = S;
    #pragma unroll
    for (int o = 1; o < 32; o <<= 1) {
        unsigned int y = __shfl_up_sync(0xFFFFFFFFu, x, o);
        if ((t & 31) >= o) x += y;
    }
    if ((t & 31) == 31) warp_sums[t >> 5] = x;
    __syncthreads();
    if (t == 0) {
        unsigned int run = 0;
        #pragma unroll
        for (int i = 0; i < 8; i++) { unsigned int v = warp_sums[i]; warp_sums[i] = run; run += v; }
        s_total = run;
    }
    __syncthreads();
    unsigned int excl = (x - S) + warp_sums[t >> 5];

    unsigned int run = excl;
    #pragma unroll
    for (int i = 0; i < 8; i++) {
        unsigned int nxt = run + c[i];
        if (run < (unsigned)K && nxt >= (unsigned)K) {
            g_cut[b] = NBINS-1 - (t*8 + i);     // exactly one thread hits the crossing
        }
        run = nxt;
    }
    if (t == 0) {
        if (s_total < (unsigned)K) g_cut[b] = 0;  // fewer than K candidates: take all
        g_cnt[b] = 0u;
    }
}

// ---------------------------------------------------------------- kernel 3: compact candidates in bins >= cut
__global__ void compact_kernel(const float* __restrict__ sCls) {
    const int b = blockIdx.y;
    const int cut = g_cut[b];
    const float4* p = (const float4*)(sCls + (size_t)b * TOT);
    const int nv4 = TOT / 4;
    const int per = nv4 / gridDim.x;
    const int start = blockIdx.x * per;
    for (int i = start + threadIdx.x; i < start + per; i += blockDim.x) {
        float4 v = p[i];
        float vv[4] = {v.x, v.y, v.z, v.w};
        #pragma unroll
        for (int j = 0; j < 4; j++) {
            float s = sigm(vv[j]);
            if (s > TH) {
                unsigned int sb  = __float_as_uint(s);
                unsigned int bin = (sb - LOBITS) >> BSHIFT;
                if (bin > NBINS-1u) bin = NBINS-1u;
                if ((int)bin >= cut) {
                    unsigned int pos = atomicAdd(&g_cnt[b], 1u);
                    if (pos < CAP) {
                        int e    = i*4 + j;            // linear within [C, HW]
                        int ch   = e >> 14;            // channel (HW = 2^14)
                        int loc  = e & (HW-1);
                        unsigned int flat = (unsigned)(loc*C + ch);
                        g_buf[b*CAP + pos] =
                            ((unsigned long long)sb << 32) | (unsigned long long)(~flat);
                    }
                }
            }
        }
    }
}

// ---------------------------------------------------------------- kernel 4: sort (bitonic desc) + decode + emit
__global__ void __launch_bounds__(1024)
emit_kernel(const float* __restrict__ sReg,
            const float* __restrict__ anchors,
            float* __restrict__ out) {
    const int b   = blockIdx.x;
    const int tid = threadIdx.x;
    __shared__ unsigned long long sk[CAP];

    unsigned int cnt = g_cnt[b];
    if (cnt > CAP) cnt = CAP;

    for (int i = tid; i < CAP; i += blockDim.x)
        sk[i] = (i < (int)cnt) ? g_buf[b*CAP + i] : 0ULL;
    __syncthreads();

    // bitonic sort, descending
    for (int size = 2; size <= CAP; size <<= 1) {
        for (int stride = size >> 1; stride > 0; stride >>= 1) {
            __syncthreads();
            for (int i = tid; i < CAP; i += blockDim.x) {
                int j = i ^ stride;
                if (j > i) {
                    bool descSeg = ((i & size) == 0);
                    unsigned long long a = sk[i], bb = sk[j];
                    bool swap = descSeg ? (a < bb) : (a > bb);
                    if (swap) { sk[i] = bb; sk[j] = a; }
                }
            }
        }
    }
    __syncthreads();

    // emit top-K
    for (int k = tid; k < K; k += blockDim.x) {
        float* det = out + ((size_t)b*K + k) * 16;
        float* lab = out + (size_t)Nb*K*16 + (size_t)b*K + k;
        float* sco = out + (size_t)Nb*K*17 + (size_t)b*K + k;
        if (k < (int)cnt) {
            unsigned long long key = sk[k];
            unsigned int sb  = (unsigned int)(key >> 32);
            unsigned int idx = ~(unsigned int)(key & 0xFFFFFFFFu);
            float s = __uint_as_float(sb);
            int loc = idx / C;
            int cls = idx - loc * C;
            const float* anc = anchors + (size_t)loc * 4;
            float x0 = anc[0], y0 = anc[1], x1 = anc[2], y1 = anc[3];
            float wa = x1 - x0, ha = y1 - y0;
            float cx = 0.5f*(x0 + x1), cy = 0.5f*(y0 + y1);
            const float* regp = sReg + ((size_t)b*(C*16) + (size_t)cls*16) * HW + loc;
            #pragma unroll
            for (int j = 0; j < 8; j++)
                det[j] = regp[(size_t)j * HW] * wa + cx;
            #pragma unroll
            for (int j = 0; j < 8; j++)
                det[8 + j] = regp[(size_t)(8 + j) * HW] * ha + cy;
            *lab = (float)(cls + 1);
            *sco = sqrtf(s);
        } else {
            #pragma unroll
            for (int j = 0; j < 16; j++) det[j] = 0.0f;
            *lab = 0.0f;
            *sco = 0.0f;
        }
    }
}

// ---------------------------------------------------------------- launcher
extern "C" void kernel_launch(void* const* d_in, const int* in_sizes, int n_in,
                              void* d_out, int out_size) {
    const float* sCls    = (const float*)d_in[0];
    const float* sReg    = (const float*)d_in[1];
    const float* anchors = (const float*)d_in[2];
    float* out = (float*)d_out;

    zero_kernel<<<(Nb*NBINS + 255)/256, 256>>>();
    {
        dim3 grid(32, Nb);
        hist_kernel<<<grid, 256>>>(sCls);
    }
    cut_kernel<<<Nb, 256>>>();
    {
        dim3 grid(32, Nb);
        compact_kernel<<<grid, 256>>>(sCls);
    }
    emit_kernel<<<Nb, 1024>>>(sReg, anchors, out);
}

// round 8
// speedup vs baseline: 1.2776x; 1.2776x over previous
#include <cuda_runtime.h>
#include <cstdint>

// Problem constants (fixed shapes)
#define Nb    16
#define C     30
#define H     128
#define W     128
#define HW    (H*W)            // 16384
#define TOT   (HW*C)           // 491520 per batch
#define K     1000
#define NBINS 1024
#define BSHIFT 14
#define LOBITS 0x3E99999Au     // __float_as_uint(0.3f)
#define CAP   2048
#define TH    0.3f
#define XTH   (-0.8473f)       // logit(0.3) = -0.84729786; slightly below, safe pre-filter

// Static scratch (no allocations allowed; zero-initialized at module load)
__device__ unsigned int       g_hist[Nb*NBINS];          // zeroed by cut_kernel after use
__device__ unsigned int       g_na[Nb];                  // zeroed by sort_kernel after use
__device__ int                g_cut[Nb];
__device__ unsigned int       g_sel[Nb];
__device__ unsigned long long g_all[(size_t)Nb*TOT];     // worst-case candidate store
__device__ unsigned long long g_top[Nb*K];

__device__ __forceinline__ float sigm(float x) {
    return 1.0f / (1.0f + expf(-x));   // must stay expf: score rounding defines the ordering
}

// ---------------------------------------------------------------- kernel 1:
// single streaming pass: histogram score bits AND compact all >TH candidates
__global__ void __launch_bounds__(256)
histcompact_kernel(const float* __restrict__ sCls) {
    __shared__ unsigned int       sh[NBINS];     // 4 KB
    __shared__ unsigned long long lst[2048];     // 16 KB (capacity == chunk elem count)
    __shared__ unsigned int       scnt, sbase;

    const int b   = blockIdx.y;
    const int tid = threadIdx.x;
    for (int i = tid; i < NBINS; i += 256) sh[i] = 0u;

    const float4* p  = (const float4*)(sCls + (size_t)b * TOT);
    const int nv4    = TOT / 4;               // 122880
    const int per    = nv4 / gridDim.x;       // gridDim.x = 128 -> 960
    const int start  = blockIdx.x * per;
    const int endf4  = start + per;

    for (int cs = start; cs < endf4; cs += 512) {          // chunk = 512 f4 = 2048 elems
        if (tid == 0) scnt = 0u;
        __syncthreads();
        const int ce = (cs + 512 < endf4) ? (cs + 512) : endf4;
        for (int i = cs + tid; i < ce; i += 256) {
            float4 v = p[i];
            float vv[4] = {v.x, v.y, v.z, v.w};
            #pragma unroll
            for (int j = 0; j < 4; j++) {
                if (vv[j] > XTH) {
                    float s = sigm(vv[j]);
                    if (s > TH) {
                        unsigned int sb  = __float_as_uint(s);
                        unsigned int bin = (sb - LOBITS) >> BSHIFT;
                        if (bin > NBINS-1u) bin = NBINS-1u;
                        atomicAdd(&sh[bin], 1u);
                        unsigned int pos = atomicAdd(&scnt, 1u);
                        int e   = i*4 + j;                 // linear within [C, HW]
                        int ch  = e >> 14;                 // channel (HW = 2^14)
                        int loc = e & (HW-1);
                        unsigned int flat = (unsigned)(loc*C + ch);
                        lst[pos] = ((unsigned long long)sb << 32) |
                                   (unsigned long long)(~flat);
                    }
                }
            }
        }
        __syncthreads();
        if (tid == 0) sbase = atomicAdd(&g_na[b], scnt);
        __syncthreads();
        const unsigned int n = scnt;
        for (unsigned int j = tid; j < n; j += 256)
            g_all[(size_t)b*TOT + sbase + j] = lst[j];
        __syncthreads();
    }

    for (int i = tid; i < NBINS; i += 256) {
        unsigned int c = sh[i];
        if (c) atomicAdd(&g_hist[b*NBINS + i], c);
    }
}

// ---------------------------------------------------------------- kernel 2:
// find cut bin (descending scan over bins), then re-zero this batch's hist
__global__ void cut_kernel() {
    const int b = blockIdx.x;        // 16 blocks, 256 threads
    const int t = threadIdx.x;
    __shared__ unsigned int warp_sums[8];
    __shared__ unsigned int s_total;

    unsigned int c[4];
    unsigned int S = 0;
    const int base = b * NBINS;
    #pragma unroll
    for (int i = 0; i < 4; i++) {
        int r = t*4 + i;                          // r=0 is the highest bin
        c[i] = g_hist[base + (NBINS-1 - r)];
        S += c[i];
    }
    unsigned int x = S;
    #pragma unroll
    for (int o = 1; o < 32; o <<= 1) {
        unsigned int y = __shfl_up_sync(0xFFFFFFFFu, x, o);
        if ((t & 31) >= o) x += y;
    }
    if ((t & 31) == 31) warp_sums[t >> 5] = x;
    __syncthreads();
    if (t == 0) {
        unsigned int run = 0;
        #pragma unroll
        for (int i = 0; i < 8; i++) { unsigned int v = warp_sums[i]; warp_sums[i] = run; run += v; }
        s_total = run;
    }
    __syncthreads();
    unsigned int excl = (x - S) + warp_sums[t >> 5];

    unsigned int run = excl;
    #pragma unroll
    for (int i = 0; i < 4; i++) {
        unsigned int nxt = run + c[i];
        if (run < (unsigned)K && nxt >= (unsigned)K)
            g_cut[b] = NBINS-1 - (t*4 + i);       // exactly one thread crosses K
        run = nxt;
    }
    if (t == 0 && s_total < (unsigned)K) g_cut[b] = 0;   // fewer than K: take all

    // restore invariant for the next graph replay
    #pragma unroll
    for (int i = 0; i < 4; i++) g_hist[base + t*4 + i] = 0u;
}

// ---------------------------------------------------------------- kernel 3:
// filter candidates (bin >= cut) from L2-resident list, bitonic sort, store top-K
__global__ void __launch_bounds__(1024)
sort_kernel() {
    const int b   = blockIdx.x;
    const int tid = threadIdx.x;
    __shared__ unsigned long long sk[CAP];       // 16 KB
    __shared__ unsigned int scnt;

    unsigned int na = g_na[b];
    const int cut   = g_cut[b];

    for (int i = tid; i < CAP; i += 1024) sk[i] = 0ULL;
    if (tid == 0) scnt = 0u;
    __syncthreads();

    const unsigned long long* src = &g_all[(size_t)b*TOT];
    #pragma unroll 4
    for (unsigned int i = tid; i < na; i += 1024) {
        unsigned long long key = __ldg(&src[i]);
        unsigned int sb  = (unsigned int)(key >> 32);
        unsigned int bin = (sb - LOBITS) >> BSHIFT;
        if (bin > NBINS-1u) bin = NBINS-1u;
        if ((int)bin >= cut) {
            unsigned int pos = atomicAdd(&scnt, 1u);
            if (pos < CAP) sk[pos] = key;
        }
    }
    __syncthreads();

    // bitonic sort, descending (keys are unique: score bits + ~flat index)
    for (int size = 2; size <= CAP; size <<= 1) {
        for (int stride = size >> 1; stride > 0; stride >>= 1) {
            __syncthreads();
            #pragma unroll
            for (int i = tid; i < CAP; i += 1024) {
                int j = i ^ stride;
                if (j > i) {
                    bool descSeg = ((i & size) == 0);
                    unsigned long long a = sk[i], bb = sk[j];
                    if (descSeg ? (a < bb) : (a > bb)) { sk[i] = bb; sk[j] = a; }
                }
            }
        }
    }
    __syncthreads();

    for (int k = tid; k < K; k += 1024) g_top[b*K + k] = sk[k];
    if (tid == 0) {
        unsigned int sel = scnt;
        g_sel[b] = (sel > (unsigned)K) ? (unsigned)K : sel;
        g_na[b]  = 0u;                            // restore invariant
    }
}

// ---------------------------------------------------------------- kernel 4:
// decode + scattered sReg gather + anchor decode + write (parallel over all rows)
__global__ void __launch_bounds__(128)
emit_kernel(const float* __restrict__ sReg,
            const float* __restrict__ anchors,
            float* __restrict__ out) {
    const int bx = blockIdx.x;                   // 128 blocks: 16 batches x 8
    const int b  = bx >> 3;
    const int k  = (bx & 7) * 128 + threadIdx.x; // 0..1023
    if (k >= K) return;

    float* det = out + ((size_t)b*K + k) * 16;
    float* lab = out + (size_t)Nb*K*16 + (size_t)b*K + k;
    float* sco = out + (size_t)Nb*K*17 + (size_t)b*K + k;

    if (k < (int)g_sel[b]) {
        unsigned long long key = g_top[b*K + k];
        unsigned int sb  = (unsigned int)(key >> 32);
        unsigned int idx = ~(unsigned int)(key & 0xFFFFFFFFu);
        float s  = __uint_as_float(sb);
        int loc  = idx / C;
        int cls  = idx - loc * C;
        float4 anc = ((const float4*)anchors)[loc];
        float wa = anc.z - anc.x, ha = anc.w - anc.y;
        float cx = 0.5f*(anc.x + anc.z), cy = 0.5f*(anc.y + anc.w);
        const float* regp = sReg + ((size_t)b*(C*16) + (size_t)cls*16) * HW + loc;
        float r[16];
        #pragma unroll
        for (int j = 0; j < 16; j++) r[j] = __ldg(&regp[(size_t)j * HW]);
        float o[16];
        #pragma unroll
        for (int j = 0; j < 8; j++)  o[j]     = r[j]     * wa + cx;
        #pragma unroll
        for (int j = 0; j < 8; j++)  o[8 + j] = r[8 + j] * ha + cy;
        #pragma unroll
        for (int j = 0; j < 4; j++)
            ((float4*)det)[j] = make_float4(o[4*j], o[4*j+1], o[4*j+2], o[4*j+3]);
        *lab = (float)(cls + 1);
        *sco = sqrtf(s);
    } else {
        #pragma unroll
        for (int j = 0; j < 4; j++)
            ((float4*)det)[j] = make_float4(0.f, 0.f, 0.f, 0.f);
        *lab = 0.0f;
        *sco = 0.0f;
    }
}

// ---------------------------------------------------------------- launcher
extern "C" void kernel_launch(void* const* d_in, const int* in_sizes, int n_in,
                              void* d_out, int out_size) {
    const float* sCls    = (const float*)d_in[0];
    const float* sReg    = (const float*)d_in[1];
    const float* anchors = (const float*)d_in[2];
    float* out = (float*)d_out;

    {
        dim3 grid(128, Nb);                  // 2048 blocks
        histcompact_kernel<<<grid, 256>>>(sCls);
    }
    cut_kernel<<<Nb, 256>>>();
    sort_kernel<<<Nb, 1024>>>();
    emit_kernel<<<Nb*8, 128>>>(sReg, anchors, out);
}